// round 1
// baseline (speedup 1.0000x reference)
#include <cuda_runtime.h>
#include <cstdint>

#define MAXN 100000
#define DHID 128

// Scratch (device globals — no runtime allocation allowed)
__device__ float g_x1[(size_t)MAXN * DHID];
__device__ float g_x2[(size_t)MAXN * DHID];
__device__ float g_agg[(size_t)MAXN * DHID];
__device__ float g_deg[MAXN];

// ---------------------------------------------------------------------------
// small helpers
// ---------------------------------------------------------------------------
__global__ void zero_kernel(float* __restrict__ p, int n4) {
    int i = blockIdx.x * blockDim.x + threadIdx.x;
    if (i < n4) reinterpret_cast<float4*>(p)[i] = make_float4(0.f, 0.f, 0.f, 0.f);
}

__global__ void deg_kernel(const int* __restrict__ dst, float* __restrict__ deg, int E) {
    int e = blockIdx.x * blockDim.x + threadIdx.x;
    if (e < E) atomicAdd(&deg[dst[e]], 1.0f);
}

__global__ void deginv_kernel(float* __restrict__ deg, int N) {
    int i = blockIdx.x * blockDim.x + threadIdx.x;
    if (i < N) {
        float d = deg[i];
        deg[i] = (d > 0.f) ? (1.0f / d) : 0.0f;
    }
}

// ---------------------------------------------------------------------------
// scatter: one warp per edge, each lane handles 4 floats (float4).
// agg[dst] += x[src] * edge_w  via red.global.add.v4.f32 (no return trip)
// ---------------------------------------------------------------------------
__global__ void scatter_kernel(const float* __restrict__ x,
                               const int* __restrict__ src,
                               const int* __restrict__ dst,
                               const float* __restrict__ ew,
                               float* __restrict__ agg, int E) {
    int t = blockIdx.x * blockDim.x + threadIdx.x;
    int e = t >> 5;
    int lane = t & 31;
    if (e >= E) return;
    int s = src[e];
    int d = dst[e];
    float w = ew[e];
    float4 v = *reinterpret_cast<const float4*>(x + (size_t)s * DHID + lane * 4);
    float* ap = agg + (size_t)d * DHID + lane * 4;
    asm volatile("red.global.add.v4.f32 [%0], {%1,%2,%3,%4};"
                 :: "l"(ap), "f"(v.x * w), "f"(v.y * w), "f"(v.z * w), "f"(v.w * w)
                 : "memory");
}

// ---------------------------------------------------------------------------
// fused combine + GEMM:  out = ((1+eps)*x + agg*deg_inv) @ W^T + b  [+relu]
// Block tile: 64 rows x 128 cols, 256 threads, 8x4 register tile per thread.
// smem: Wt[128][128] (64KB) + yT[128][64] (32KB) = 96KB dynamic.
// ---------------------------------------------------------------------------
__global__ void __launch_bounds__(256)
gemm_kernel(const float* __restrict__ x, const float* __restrict__ agg,
            const float* __restrict__ deg_inv,
            const float* __restrict__ W, const float* __restrict__ b,
            const float* __restrict__ eps_ptr, int eps_idx,
            float* __restrict__ out, int n_rows, int do_relu, int zero_row0) {
    extern __shared__ float smem[];
    float* Wt = smem;               // Wt[k][col], stride 128
    float* yT = smem + 128 * 128;   // yT[k][row], stride 64

    int tid = threadIdx.x;

    // Load W (row-major [128 out][128 in]) transposed into Wt[k][col]
#pragma unroll
    for (int i = 0; i < 16; i++) {
        int idx = tid + i * 256;        // float4 chunk id, 0..4095
        int c = idx & 127;              // output col (W row)
        int k4 = (idx >> 7) * 4;        // k base
        float4 w4 = *reinterpret_cast<const float4*>(W + (size_t)c * 128 + k4);
        Wt[(k4 + 0) * 128 + c] = w4.x;
        Wt[(k4 + 1) * 128 + c] = w4.y;
        Wt[(k4 + 2) * 128 + c] = w4.z;
        Wt[(k4 + 3) * 128 + c] = w4.w;
    }

    float epsv = 1.0f + eps_ptr[eps_idx];

    int row0 = blockIdx.x * 64;
    int r = tid & 63;                  // row within tile
    int cq = tid >> 6;                 // 0..3 column quarter (32 floats)
    int grow = row0 + r;
    float dinv = (grow < n_rows) ? deg_inv[grow] : 0.0f;

#pragma unroll
    for (int j = 0; j < 8; j++) {
        int k4 = cq * 32 + j * 4;
        float4 xv = make_float4(0.f, 0.f, 0.f, 0.f);
        float4 av = xv;
        if (grow < n_rows) {
            xv = *reinterpret_cast<const float4*>(x + (size_t)grow * 128 + k4);
            av = *reinterpret_cast<const float4*>(agg + (size_t)grow * 128 + k4);
        }
        yT[(k4 + 0) * 64 + r] = epsv * xv.x + av.x * dinv;
        yT[(k4 + 1) * 64 + r] = epsv * xv.y + av.y * dinv;
        yT[(k4 + 2) * 64 + r] = epsv * xv.z + av.z * dinv;
        yT[(k4 + 3) * 64 + r] = epsv * xv.w + av.w * dinv;
    }
    __syncthreads();

    int tx = tid & 31;                 // col group: cols tx*4 .. +3
    int ty = tid >> 5;                 // row group: rows ty*8 .. +7

    float acc[8][4];
#pragma unroll
    for (int i = 0; i < 8; i++)
#pragma unroll
        for (int j = 0; j < 4; j++) acc[i][j] = 0.f;

#pragma unroll 4
    for (int k = 0; k < 128; k++) {
        float4 wv = *reinterpret_cast<float4*>(&Wt[k * 128 + tx * 4]);
        float4 y0 = *reinterpret_cast<float4*>(&yT[k * 64 + ty * 8]);
        float4 y1 = *reinterpret_cast<float4*>(&yT[k * 64 + ty * 8 + 4]);
        float ys[8] = {y0.x, y0.y, y0.z, y0.w, y1.x, y1.y, y1.z, y1.w};
#pragma unroll
        for (int i = 0; i < 8; i++) {
            acc[i][0] += ys[i] * wv.x;
            acc[i][1] += ys[i] * wv.y;
            acc[i][2] += ys[i] * wv.z;
            acc[i][3] += ys[i] * wv.w;
        }
    }

    float4 bv = *reinterpret_cast<const float4*>(b + tx * 4);
#pragma unroll
    for (int i = 0; i < 8; i++) {
        int orow = row0 + ty * 8 + i;
        if (orow >= n_rows) continue;
        float4 o;
        o.x = acc[i][0] + bv.x;
        o.y = acc[i][1] + bv.y;
        o.z = acc[i][2] + bv.z;
        o.w = acc[i][3] + bv.w;
        if (do_relu) {
            o.x = fmaxf(o.x, 0.f); o.y = fmaxf(o.y, 0.f);
            o.z = fmaxf(o.z, 0.f); o.w = fmaxf(o.w, 0.f);
        }
        if (zero_row0 && orow == 0) o = make_float4(0.f, 0.f, 0.f, 0.f);
        *reinterpret_cast<float4*>(out + (size_t)orow * 128 + tx * 4) = o;
    }
}

// ---------------------------------------------------------------------------
extern "C" void kernel_launch(void* const* d_in, const int* in_sizes, int n_in,
                              void* d_out, int out_size) {
    const float* emb    = (const float*)d_in[0];
    const float* w1     = (const float*)d_in[1];
    const float* b1     = (const float*)d_in[2];
    const float* w2     = (const float*)d_in[3];
    const float* b2     = (const float*)d_in[4];
    const float* eps    = (const float*)d_in[5];
    const float* edge_w = (const float*)d_in[6];
    const int*   src    = (const int*)d_in[7];
    const int*   dst    = (const int*)d_in[8];

    int N = in_sizes[0] / DHID;
    int E = in_sizes[6];
    float* out = (float*)d_out;

    float *x1, *x2, *agg, *deg;
    cudaGetSymbolAddress((void**)&x1,  g_x1);
    cudaGetSymbolAddress((void**)&x2,  g_x2);
    cudaGetSymbolAddress((void**)&agg, g_agg);
    cudaGetSymbolAddress((void**)&deg, g_deg);

    static bool attr_set = false;
    if (!attr_set) {
        cudaFuncSetAttribute(gemm_kernel,
                             cudaFuncAttributeMaxDynamicSharedMemorySize, 98304);
        attr_set = true;
    }

    const int SMEM = 98304;
    int feat4 = N * DHID / 4;             // float4 count of a feature buffer
    int gz_feat = (feat4 + 255) / 256;
    int gz_deg  = (N / 4 + 255) / 256;    // N=100000 divisible by 4
    int g_edges = (E + 255) / 256;
    int g_scat  = ((size_t)E * 32 + 255) / 256;
    int g_node  = (N + 255) / 256;
    int g_gemm  = (N + 63) / 64;

    // in-degree -> deg_inv (stored back into g_deg)
    zero_kernel<<<gz_deg, 256>>>(deg, N / 4);
    deg_kernel<<<g_edges, 256>>>(dst, deg, E);
    deginv_kernel<<<g_node, 256>>>(deg, N);

    // layer 1: emb -> x1 (relu)
    zero_kernel<<<gz_feat, 256>>>(agg, feat4);
    scatter_kernel<<<g_scat, 256>>>(emb, src, dst, edge_w, agg, E);
    gemm_kernel<<<g_gemm, 256, SMEM>>>(emb, agg, deg, w1, b1, eps, 0, x1, N, 1, 0);

    // layer 2: x1 -> x2 (relu)
    zero_kernel<<<gz_feat, 256>>>(agg, feat4);
    scatter_kernel<<<g_scat, 256>>>(x1, src, dst, edge_w, agg, E);
    gemm_kernel<<<g_gemm, 256, SMEM>>>(x1, agg, deg, w2, b2, eps, 1, x2, N, 1, 0);

    // layer 3: x2 -> out (no relu, row 0 zeroed)
    zero_kernel<<<gz_feat, 256>>>(agg, feat4);
    scatter_kernel<<<g_scat, 256>>>(x2, src, dst, edge_w, agg, E);
    gemm_kernel<<<g_gemm, 256, SMEM>>>(x2, agg, deg, w2, b2, eps, 2, out, N, 0, 1);
}

// round 2
// speedup vs baseline: 1.7498x; 1.7498x over previous
#include <cuda_runtime.h>
#include <cstdint>

#define MAXN 100000
#define MAXE 1600000
#define DHID 128
#define SCAN_B 1024
#define MAXBLK 128   // >= ceil(MAXN/SCAN_B) = 98

// Scratch (device globals — no runtime allocation allowed)
__device__ float g_x1[(size_t)MAXN * DHID];
__device__ float g_x2[(size_t)MAXN * DHID];
__device__ int   g_cnt[MAXN];        // in-degree (int)
__device__ int   g_incl[MAXN];       // inclusive scan within block
__device__ int   g_rowstart[MAXN];   // CSR row start
__device__ int   g_cursor[MAXN];     // fill cursors
__device__ int   g_bsums[MAXBLK];    // per-block sums
__device__ int   g_boffs[MAXBLK];    // exclusive block offsets
__device__ int   g_col[MAXE];        // CSR: src per edge slot
__device__ float g_w[MAXE];          // CSR: weight per edge slot

// ---------------------------------------------------------------------------
// CSR build
// ---------------------------------------------------------------------------
__global__ void zero_int_kernel(int* __restrict__ p, int n4) {
    int i = blockIdx.x * blockDim.x + threadIdx.x;
    if (i < n4) reinterpret_cast<int4*>(p)[i] = make_int4(0, 0, 0, 0);
}

__global__ void count_kernel(const int* __restrict__ dst, int* __restrict__ cnt, int E) {
    int e = blockIdx.x * blockDim.x + threadIdx.x;
    if (e < E) atomicAdd(&cnt[dst[e]], 1);
}

__global__ void __launch_bounds__(SCAN_B)
scan1_kernel(const int* __restrict__ cnt, int* __restrict__ incl,
             int* __restrict__ bsums, int N) {
    __shared__ int s[SCAN_B];
    int tid = threadIdx.x;
    int i = blockIdx.x * SCAN_B + tid;
    int v = (i < N) ? cnt[i] : 0;
    s[tid] = v;
    __syncthreads();
#pragma unroll
    for (int off = 1; off < SCAN_B; off <<= 1) {
        int t = (tid >= off) ? s[tid - off] : 0;
        __syncthreads();
        s[tid] += t;
        __syncthreads();
    }
    if (i < N) incl[i] = s[tid];
    if (tid == SCAN_B - 1) bsums[blockIdx.x] = s[tid];
}

__global__ void __launch_bounds__(MAXBLK)
scan2_kernel(const int* __restrict__ bsums, int* __restrict__ boffs, int nb) {
    __shared__ int s[MAXBLK];
    int tid = threadIdx.x;
    int v = (tid < nb) ? bsums[tid] : 0;
    s[tid] = v;
    __syncthreads();
#pragma unroll
    for (int off = 1; off < MAXBLK; off <<= 1) {
        int t = (tid >= off) ? s[tid - off] : 0;
        __syncthreads();
        s[tid] += t;
        __syncthreads();
    }
    boffs[tid] = s[tid] - v;   // exclusive
}

__global__ void scan3_kernel(const int* __restrict__ incl, const int* __restrict__ cnt,
                             const int* __restrict__ boffs,
                             int* __restrict__ rowstart, int* __restrict__ cursor, int N) {
    int i = blockIdx.x * blockDim.x + threadIdx.x;
    if (i < N) {
        int rs = incl[i] - cnt[i] + boffs[i / SCAN_B];
        rowstart[i] = rs;
        cursor[i] = rs;
    }
}

__global__ void fill_kernel(const int* __restrict__ src, const int* __restrict__ dst,
                            const float* __restrict__ ew,
                            int* __restrict__ cursor,
                            int* __restrict__ col, float* __restrict__ w, int E) {
    int e = blockIdx.x * blockDim.x + threadIdx.x;
    if (e < E) {
        int pos = atomicAdd(&cursor[dst[e]], 1);
        col[pos] = src[e];
        w[pos] = ew[e];
    }
}

// ---------------------------------------------------------------------------
// aggregation + combine:  y = (1+eps)*x + (mean over in-edges of x[src]*w)
// one warp per node, each lane owns 4 features.
// ---------------------------------------------------------------------------
__global__ void __launch_bounds__(256)
agg_kernel(const float* __restrict__ x,
           const int* __restrict__ rowstart, const int* __restrict__ cnt,
           const int* __restrict__ col, const float* __restrict__ w,
           const float* __restrict__ eps_ptr, int eps_idx,
           float* __restrict__ y, int N) {
    int t = blockIdx.x * blockDim.x + threadIdx.x;
    int node = t >> 5;
    int lane = t & 31;
    if (node >= N) return;

    int start = rowstart[node];
    int c = cnt[node];

    float4 a0 = make_float4(0.f, 0.f, 0.f, 0.f);
    float4 a1 = a0;
    int j = 0;
    for (; j + 1 < c; j += 2) {
        int c0 = __ldg(&col[start + j]);
        int c1 = __ldg(&col[start + j + 1]);
        float w0 = __ldg(&w[start + j]);
        float w1 = __ldg(&w[start + j + 1]);
        float4 v0 = __ldg(reinterpret_cast<const float4*>(x + (size_t)c0 * DHID + lane * 4));
        float4 v1 = __ldg(reinterpret_cast<const float4*>(x + (size_t)c1 * DHID + lane * 4));
        a0.x += v0.x * w0; a0.y += v0.y * w0; a0.z += v0.z * w0; a0.w += v0.w * w0;
        a1.x += v1.x * w1; a1.y += v1.y * w1; a1.z += v1.z * w1; a1.w += v1.w * w1;
    }
    if (j < c) {
        int c0 = __ldg(&col[start + j]);
        float w0 = __ldg(&w[start + j]);
        float4 v0 = __ldg(reinterpret_cast<const float4*>(x + (size_t)c0 * DHID + lane * 4));
        a0.x += v0.x * w0; a0.y += v0.y * w0; a0.z += v0.z * w0; a0.w += v0.w * w0;
    }
    float dinv = (c > 0) ? (1.0f / (float)c) : 0.0f;
    float epsv = 1.0f + eps_ptr[eps_idx];

    float4 xv = __ldg(reinterpret_cast<const float4*>(x + (size_t)node * DHID + lane * 4));
    float4 o;
    o.x = epsv * xv.x + (a0.x + a1.x) * dinv;
    o.y = epsv * xv.y + (a0.y + a1.y) * dinv;
    o.z = epsv * xv.z + (a0.z + a1.z) * dinv;
    o.w = epsv * xv.w + (a0.w + a1.w) * dinv;
    *reinterpret_cast<float4*>(y + (size_t)node * DHID + lane * 4) = o;
}

// ---------------------------------------------------------------------------
// GEMM: out = y @ W^T + b  [+relu]  (64 rows x 128 cols per block, 256 thr)
// ---------------------------------------------------------------------------
__global__ void __launch_bounds__(256)
gemm_kernel(const float* __restrict__ y,
            const float* __restrict__ W, const float* __restrict__ b,
            float* __restrict__ out, int n_rows, int do_relu, int zero_row0) {
    extern __shared__ float smem[];
    float* Wt = smem;               // Wt[k][col], stride 128
    float* yT = smem + 128 * 128;   // yT[k][row], stride 64

    int tid = threadIdx.x;

#pragma unroll
    for (int i = 0; i < 16; i++) {
        int idx = tid + i * 256;
        int cc = idx & 127;
        int k4 = (idx >> 7) * 4;
        float4 w4 = *reinterpret_cast<const float4*>(W + (size_t)cc * 128 + k4);
        Wt[(k4 + 0) * 128 + cc] = w4.x;
        Wt[(k4 + 1) * 128 + cc] = w4.y;
        Wt[(k4 + 2) * 128 + cc] = w4.z;
        Wt[(k4 + 3) * 128 + cc] = w4.w;
    }

    int row0 = blockIdx.x * 64;
    int r = tid & 63;
    int cq = tid >> 6;
    int grow = row0 + r;

#pragma unroll
    for (int j = 0; j < 8; j++) {
        int k4 = cq * 32 + j * 4;
        float4 v = make_float4(0.f, 0.f, 0.f, 0.f);
        if (grow < n_rows)
            v = *reinterpret_cast<const float4*>(y + (size_t)grow * 128 + k4);
        yT[(k4 + 0) * 64 + r] = v.x;
        yT[(k4 + 1) * 64 + r] = v.y;
        yT[(k4 + 2) * 64 + r] = v.z;
        yT[(k4 + 3) * 64 + r] = v.w;
    }
    __syncthreads();

    int tx = tid & 31;
    int ty = tid >> 5;

    float acc[8][4];
#pragma unroll
    for (int i = 0; i < 8; i++)
#pragma unroll
        for (int j = 0; j < 4; j++) acc[i][j] = 0.f;

#pragma unroll 4
    for (int k = 0; k < 128; k++) {
        float4 wv = *reinterpret_cast<float4*>(&Wt[k * 128 + tx * 4]);
        float4 y0 = *reinterpret_cast<float4*>(&yT[k * 64 + ty * 8]);
        float4 y1 = *reinterpret_cast<float4*>(&yT[k * 64 + ty * 8 + 4]);
        float ys[8] = {y0.x, y0.y, y0.z, y0.w, y1.x, y1.y, y1.z, y1.w};
#pragma unroll
        for (int i = 0; i < 8; i++) {
            acc[i][0] += ys[i] * wv.x;
            acc[i][1] += ys[i] * wv.y;
            acc[i][2] += ys[i] * wv.z;
            acc[i][3] += ys[i] * wv.w;
        }
    }

    float4 bv = *reinterpret_cast<const float4*>(b + tx * 4);
#pragma unroll
    for (int i = 0; i < 8; i++) {
        int orow = row0 + ty * 8 + i;
        if (orow >= n_rows) continue;
        float4 o;
        o.x = acc[i][0] + bv.x;
        o.y = acc[i][1] + bv.y;
        o.z = acc[i][2] + bv.z;
        o.w = acc[i][3] + bv.w;
        if (do_relu) {
            o.x = fmaxf(o.x, 0.f); o.y = fmaxf(o.y, 0.f);
            o.z = fmaxf(o.z, 0.f); o.w = fmaxf(o.w, 0.f);
        }
        if (zero_row0 && orow == 0) o = make_float4(0.f, 0.f, 0.f, 0.f);
        *reinterpret_cast<float4*>(out + (size_t)orow * 128 + tx * 4) = o;
    }
}

// ---------------------------------------------------------------------------
extern "C" void kernel_launch(void* const* d_in, const int* in_sizes, int n_in,
                              void* d_out, int out_size) {
    const float* emb    = (const float*)d_in[0];
    const float* w1     = (const float*)d_in[1];
    const float* b1     = (const float*)d_in[2];
    const float* w2     = (const float*)d_in[3];
    const float* b2     = (const float*)d_in[4];
    const float* eps    = (const float*)d_in[5];
    const float* edge_w = (const float*)d_in[6];
    const int*   src    = (const int*)d_in[7];
    const int*   dst    = (const int*)d_in[8];

    int N = in_sizes[0] / DHID;
    int E = in_sizes[6];
    float* out = (float*)d_out;

    float *x1, *x2, *csr_w;
    int *cnt, *incl, *rowstart, *cursor, *bsums, *boffs, *csr_col;
    cudaGetSymbolAddress((void**)&x1, g_x1);
    cudaGetSymbolAddress((void**)&x2, g_x2);
    cudaGetSymbolAddress((void**)&cnt, g_cnt);
    cudaGetSymbolAddress((void**)&incl, g_incl);
    cudaGetSymbolAddress((void**)&rowstart, g_rowstart);
    cudaGetSymbolAddress((void**)&cursor, g_cursor);
    cudaGetSymbolAddress((void**)&bsums, g_bsums);
    cudaGetSymbolAddress((void**)&boffs, g_boffs);
    cudaGetSymbolAddress((void**)&csr_col, g_col);
    cudaGetSymbolAddress((void**)&csr_w, g_w);

    static bool attr_set = false;
    if (!attr_set) {
        cudaFuncSetAttribute(gemm_kernel,
                             cudaFuncAttributeMaxDynamicSharedMemorySize, 98304);
        attr_set = true;
    }

    const int SMEM = 98304;
    int nb = (N + SCAN_B - 1) / SCAN_B;
    int g_edges = (E + 255) / 256;
    int g_node  = (N + 255) / 256;
    int g_agg   = ((size_t)N * 32 + 255) / 256;
    int g_gemm  = (N + 63) / 64;

    // ---- CSR build ----
    zero_int_kernel<<<(N / 4 + 255) / 256, 256>>>(cnt, N / 4);
    count_kernel<<<g_edges, 256>>>(dst, cnt, E);
    scan1_kernel<<<nb, SCAN_B>>>(cnt, incl, bsums, N);
    scan2_kernel<<<1, MAXBLK>>>(bsums, boffs, nb);
    scan3_kernel<<<g_node, 256>>>(incl, cnt, boffs, rowstart, cursor, N);
    fill_kernel<<<g_edges, 256>>>(src, dst, edge_w, cursor, csr_col, csr_w, E);

    // ---- layer 1: emb -> x1 (relu) ----
    agg_kernel<<<g_agg, 256>>>(emb, rowstart, cnt, csr_col, csr_w, eps, 0, x2, N);
    gemm_kernel<<<g_gemm, 256, SMEM>>>(x2, w1, b1, x1, N, 1, 0);

    // ---- layer 2: x1 -> x2 (relu) ----
    agg_kernel<<<g_agg, 256>>>(x1, rowstart, cnt, csr_col, csr_w, eps, 1, x2, N);
    gemm_kernel<<<g_gemm, 256, SMEM>>>(x2, w2, b2, x1, N, 1, 0);

    // ---- layer 3: x1 -> out (no relu, row 0 zeroed) ----
    agg_kernel<<<g_agg, 256>>>(x1, rowstart, cnt, csr_col, csr_w, eps, 2, x2, N);
    gemm_kernel<<<g_gemm, 256, SMEM>>>(x2, w2, b2, out, N, 0, 1);
}

// round 4
// speedup vs baseline: 2.3063x; 1.3180x over previous
#include <cuda_runtime.h>
#include <cuda_bf16.h>
#include <cstdint>

#define MAXN 100000
#define MAXE 1600000
#define DHID 128
#define SCAN_B 1024
#define MAXBLK 128

// ---------------------------------------------------------------------------
// Scratch (device globals)
// ---------------------------------------------------------------------------
__device__ float g_x1[(size_t)MAXN * DHID];
__device__ float g_x2[(size_t)MAXN * DHID];
__device__ int   g_cnt[MAXN];
__device__ int   g_incl[MAXN];
__device__ int   g_rowstart[MAXN];
__device__ int   g_cursor[MAXN];
__device__ int   g_bsums[MAXBLK];
__device__ int   g_boffs[MAXBLK];
__device__ int   g_col[MAXE];
__device__ float g_w[MAXE];
// bf16 weight splits, plain row-major [out 128][k 128]
__device__ unsigned short g_w1hi[16384], g_w1lo[16384];
__device__ unsigned short g_w2hi[16384], g_w2lo[16384];

// ---------------------------------------------------------------------------
// mma.sync helper (HMMA, arch-portable)
// ---------------------------------------------------------------------------
__device__ __forceinline__ void mma16816(float* c, const uint32_t* a, const uint32_t* bb) {
    asm volatile(
        "mma.sync.aligned.m16n8k16.row.col.f32.bf16.bf16.f32 "
        "{%0,%1,%2,%3}, {%4,%5,%6,%7}, {%8,%9}, {%0,%1,%2,%3};"
        : "+f"(c[0]), "+f"(c[1]), "+f"(c[2]), "+f"(c[3])
        : "r"(a[0]), "r"(a[1]), "r"(a[2]), "r"(a[3]), "r"(bb[0]), "r"(bb[1]));
}

// ---------------------------------------------------------------------------
// CSR build
// ---------------------------------------------------------------------------
__global__ void zero_int_kernel(int* __restrict__ p, int n4) {
    int i = blockIdx.x * blockDim.x + threadIdx.x;
    if (i < n4) reinterpret_cast<int4*>(p)[i] = make_int4(0, 0, 0, 0);
}

__global__ void count_kernel(const int* __restrict__ dst, int* __restrict__ cnt, int E) {
    int e = blockIdx.x * blockDim.x + threadIdx.x;
    if (e < E) atomicAdd(&cnt[dst[e]], 1);
}

__global__ void __launch_bounds__(SCAN_B)
scan1_kernel(const int* __restrict__ cnt, int* __restrict__ incl,
             int* __restrict__ bsums, int N) {
    __shared__ int s[SCAN_B];
    int tid = threadIdx.x;
    int i = blockIdx.x * SCAN_B + tid;
    int v = (i < N) ? cnt[i] : 0;
    s[tid] = v;
    __syncthreads();
#pragma unroll
    for (int off = 1; off < SCAN_B; off <<= 1) {
        int t = (tid >= off) ? s[tid - off] : 0;
        __syncthreads();
        s[tid] += t;
        __syncthreads();
    }
    if (i < N) incl[i] = s[tid];
    if (tid == SCAN_B - 1) bsums[blockIdx.x] = s[tid];
}

__global__ void __launch_bounds__(MAXBLK)
scan2_kernel(const int* __restrict__ bsums, int* __restrict__ boffs, int nb) {
    __shared__ int s[MAXBLK];
    int tid = threadIdx.x;
    int v = (tid < nb) ? bsums[tid] : 0;
    s[tid] = v;
    __syncthreads();
#pragma unroll
    for (int off = 1; off < MAXBLK; off <<= 1) {
        int t = (tid >= off) ? s[tid - off] : 0;
        __syncthreads();
        s[tid] += t;
        __syncthreads();
    }
    boffs[tid] = s[tid] - v;
}

__global__ void scan3_kernel(const int* __restrict__ incl, const int* __restrict__ cnt,
                             const int* __restrict__ boffs,
                             int* __restrict__ rowstart, int* __restrict__ cursor, int N) {
    int i = blockIdx.x * blockDim.x + threadIdx.x;
    if (i < N) {
        int rs = incl[i] - cnt[i] + boffs[i / SCAN_B];
        rowstart[i] = rs;
        cursor[i] = rs;
    }
}

__global__ void fill_kernel(const int* __restrict__ src, const int* __restrict__ dst,
                            const float* __restrict__ ew,
                            int* __restrict__ cursor,
                            int* __restrict__ col, float* __restrict__ w, int E) {
    int e = blockIdx.x * blockDim.x + threadIdx.x;
    if (e < E) {
        int pos = atomicAdd(&cursor[dst[e]], 1);
        col[pos] = src[e];
        w[pos] = ew[e];
    }
}

// ---------------------------------------------------------------------------
// weight split: W -> hi/lo bf16, plain row-major
// ---------------------------------------------------------------------------
__global__ void prep_w_kernel(const float* __restrict__ w1, const float* __restrict__ w2) {
    int idx = blockIdx.x * blockDim.x + threadIdx.x;   // 0 .. 32767
    int which = idx >> 14;
    int e = idx & 16383;
    float v = (which ? w2 : w1)[e];
    __nv_bfloat16 hb = __float2bfloat16(v);
    __nv_bfloat16 lb = __float2bfloat16(v - __bfloat162float(hb));
    if (which) { g_w2hi[e] = __bfloat16_as_ushort(hb); g_w2lo[e] = __bfloat16_as_ushort(lb); }
    else       { g_w1hi[e] = __bfloat16_as_ushort(hb); g_w1lo[e] = __bfloat16_as_ushort(lb); }
}

// ---------------------------------------------------------------------------
// aggregation + combine:  y = (1+eps)*x + mean over in-edges of x[src]*w
// ---------------------------------------------------------------------------
__global__ void __launch_bounds__(256)
agg_kernel(const float* __restrict__ x,
           const int* __restrict__ rowstart, const int* __restrict__ cnt,
           const int* __restrict__ col, const float* __restrict__ w,
           const float* __restrict__ eps_ptr, int eps_idx,
           float* __restrict__ y, int N) {
    int t = blockIdx.x * blockDim.x + threadIdx.x;
    int node = t >> 5;
    int lane = t & 31;
    if (node >= N) return;

    int start = rowstart[node];
    int c = cnt[node];

    float4 a0 = make_float4(0.f, 0.f, 0.f, 0.f);
    float4 a1 = a0;
    int j = 0;
    for (; j + 1 < c; j += 2) {
        int c0 = __ldg(&col[start + j]);
        int c1 = __ldg(&col[start + j + 1]);
        float w0 = __ldg(&w[start + j]);
        float w1 = __ldg(&w[start + j + 1]);
        float4 v0 = __ldg(reinterpret_cast<const float4*>(x + (size_t)c0 * DHID + lane * 4));
        float4 v1 = __ldg(reinterpret_cast<const float4*>(x + (size_t)c1 * DHID + lane * 4));
        a0.x += v0.x * w0; a0.y += v0.y * w0; a0.z += v0.z * w0; a0.w += v0.w * w0;
        a1.x += v1.x * w1; a1.y += v1.y * w1; a1.z += v1.z * w1; a1.w += v1.w * w1;
    }
    if (j < c) {
        int c0 = __ldg(&col[start + j]);
        float w0 = __ldg(&w[start + j]);
        float4 v0 = __ldg(reinterpret_cast<const float4*>(x + (size_t)c0 * DHID + lane * 4));
        a0.x += v0.x * w0; a0.y += v0.y * w0; a0.z += v0.z * w0; a0.w += v0.w * w0;
    }
    float dinv = (c > 0) ? (1.0f / (float)c) : 0.0f;
    float epsv = 1.0f + eps_ptr[eps_idx];

    float4 xv = __ldg(reinterpret_cast<const float4*>(x + (size_t)node * DHID + lane * 4));
    float4 o;
    o.x = epsv * xv.x + (a0.x + a1.x) * dinv;
    o.y = epsv * xv.y + (a0.y + a1.y) * dinv;
    o.z = epsv * xv.z + (a0.z + a1.z) * dinv;
    o.w = epsv * xv.w + (a0.w + a1.w) * dinv;
    *reinterpret_cast<float4*>(y + (size_t)node * DHID + lane * 4) = o;
}

// ---------------------------------------------------------------------------
// HMMA GEMM:  out = y @ W^T + b  [+relu]
// Block: 128 rows x 128 cols, 256 threads (8 warps: 4 row-groups x 2 col-groups).
// Warp tile 32x64: 2 m-frags x 8 n-frags of m16n8k16, K=128 in 8 steps.
// fp32 via split: D = Ahi*Bhi + Ahi*Blo + Alo*Bhi.
// smem: 4 tiles of 128 rows x 272B (row = 128 bf16 + 8 pad) = 139264 B.
// ---------------------------------------------------------------------------
#define PADB 272
#define SM_A_HI 0
#define SM_A_LO 34816
#define SM_B_HI 69632
#define SM_B_LO 104448
#define SM_TOT  139264

__global__ void __launch_bounds__(256)
mm_kernel(const float* __restrict__ y,
          const unsigned short* __restrict__ whi, const unsigned short* __restrict__ wlo,
          const float* __restrict__ b,
          float* __restrict__ out, int n_rows, int do_relu, int zero_row0) {
    extern __shared__ __align__(16) char sm[];
    int tid = threadIdx.x;
    int lane = tid & 31;
    int wid = tid >> 5;

    // copy W hi/lo (gmem row-major [128][128] bf16) into padded smem
    {
        const uint4* bh = reinterpret_cast<const uint4*>(whi);
        const uint4* bl = reinterpret_cast<const uint4*>(wlo);
#pragma unroll
        for (int i = 0; i < 8; i++) {
            int idx = tid + i * 256;        // 16B chunk id, 0..2047
            int row = idx >> 4;
            int c = idx & 15;
            *reinterpret_cast<uint4*>(sm + SM_B_HI + row * PADB + c * 16) = bh[idx];
            *reinterpret_cast<uint4*>(sm + SM_B_LO + row * PADB + c * 16) = bl[idx];
        }
    }

    // convert A tile: y rows -> hi/lo bf16, padded smem
    int row0 = blockIdx.x * 128;
    {
        int r = tid >> 1;
        int kb = (tid & 1) * 64;
        int grow = row0 + r;
        bool valid = (grow < n_rows);
        const float4* yp = reinterpret_cast<const float4*>(y + (size_t)grow * 128 + kb);
#pragma unroll
        for (int j = 0; j < 16; j++) {
            float4 v = valid ? __ldg(yp + j) : make_float4(0.f, 0.f, 0.f, 0.f);
            __nv_bfloat16 h0 = __float2bfloat16(v.x), h1 = __float2bfloat16(v.y);
            __nv_bfloat16 h2 = __float2bfloat16(v.z), h3 = __float2bfloat16(v.w);
            __nv_bfloat16 l0 = __float2bfloat16(v.x - __bfloat162float(h0));
            __nv_bfloat16 l1 = __float2bfloat16(v.y - __bfloat162float(h1));
            __nv_bfloat16 l2 = __float2bfloat16(v.z - __bfloat162float(h2));
            __nv_bfloat16 l3 = __float2bfloat16(v.w - __bfloat162float(h3));
            uint2 hp, lp;
            hp.x = ((uint32_t)__bfloat16_as_ushort(h1) << 16) | __bfloat16_as_ushort(h0);
            hp.y = ((uint32_t)__bfloat16_as_ushort(h3) << 16) | __bfloat16_as_ushort(h2);
            lp.x = ((uint32_t)__bfloat16_as_ushort(l1) << 16) | __bfloat16_as_ushort(l0);
            lp.y = ((uint32_t)__bfloat16_as_ushort(l3) << 16) | __bfloat16_as_ushort(l2);
            uint32_t off = (uint32_t)(r * PADB + (kb + j * 4) * 2);
            *reinterpret_cast<uint2*>(sm + SM_A_HI + off) = hp;
            *reinterpret_cast<uint2*>(sm + SM_A_LO + off) = lp;
        }
    }
    __syncthreads();

    int gid = lane >> 2;     // 0..7
    int tig = lane & 3;      // 0..3
    int wr = (wid & 3) * 32; // warp row base
    int wn = (wid >> 2) * 64;// warp col base

    const char* pAhi = sm + SM_A_HI + (wr + gid) * PADB + tig * 4;
    const char* pAlo = sm + SM_A_LO + (wr + gid) * PADB + tig * 4;
    const char* pBhi = sm + SM_B_HI + (wn + gid) * PADB + tig * 4;
    const char* pBlo = sm + SM_B_LO + (wn + gid) * PADB + tig * 4;

    float acc[2][8][4];
#pragma unroll
    for (int mt = 0; mt < 2; mt++)
#pragma unroll
        for (int nt = 0; nt < 8; nt++)
#pragma unroll
            for (int q = 0; q < 4; q++) acc[mt][nt][q] = 0.f;

#pragma unroll
    for (int k = 0; k < 8; k++) {
        int ko = k * 32;  // k*16 elems * 2B
        uint32_t ahi[2][4], alo[2][4];
#pragma unroll
        for (int mt = 0; mt < 2; mt++) {
            int mo = mt * 16 * PADB;
            ahi[mt][0] = *reinterpret_cast<const uint32_t*>(pAhi + mo + ko);
            ahi[mt][1] = *reinterpret_cast<const uint32_t*>(pAhi + mo + 8 * PADB + ko);
            ahi[mt][2] = *reinterpret_cast<const uint32_t*>(pAhi + mo + ko + 16);
            ahi[mt][3] = *reinterpret_cast<const uint32_t*>(pAhi + mo + 8 * PADB + ko + 16);
            alo[mt][0] = *reinterpret_cast<const uint32_t*>(pAlo + mo + ko);
            alo[mt][1] = *reinterpret_cast<const uint32_t*>(pAlo + mo + 8 * PADB + ko);
            alo[mt][2] = *reinterpret_cast<const uint32_t*>(pAlo + mo + ko + 16);
            alo[mt][3] = *reinterpret_cast<const uint32_t*>(pAlo + mo + 8 * PADB + ko + 16);
        }
#pragma unroll
        for (int nt = 0; nt < 8; nt++) {
            int no = nt * 8 * PADB;
            uint32_t bh[2], bl[2];
            bh[0] = *reinterpret_cast<const uint32_t*>(pBhi + no + ko);
            bh[1] = *reinterpret_cast<const uint32_t*>(pBhi + no + ko + 16);
            bl[0] = *reinterpret_cast<const uint32_t*>(pBlo + no + ko);
            bl[1] = *reinterpret_cast<const uint32_t*>(pBlo + no + ko + 16);
#pragma unroll
            for (int mt = 0; mt < 2; mt++) {
                mma16816(acc[mt][nt], ahi[mt], bh);
                mma16816(acc[mt][nt], ahi[mt], bl);
                mma16816(acc[mt][nt], alo[mt], bh);
            }
        }
    }

    // epilogue: direct gmem writes (float2 per fragment row)
#pragma unroll
    for (int nt = 0; nt < 8; nt++) {
        int colc = wn + nt * 8 + tig * 2;
        float2 bv = *reinterpret_cast<const float2*>(b + colc);
#pragma unroll
        for (int mt = 0; mt < 2; mt++) {
            int ra = row0 + wr + mt * 16 + gid;
            float2 o0, o1;
            o0.x = acc[mt][nt][0] + bv.x;
            o0.y = acc[mt][nt][1] + bv.y;
            o1.x = acc[mt][nt][2] + bv.x;
            o1.y = acc[mt][nt][3] + bv.y;
            if (do_relu) {
                o0.x = fmaxf(o0.x, 0.f); o0.y = fmaxf(o0.y, 0.f);
                o1.x = fmaxf(o1.x, 0.f); o1.y = fmaxf(o1.y, 0.f);
            }
            if (zero_row0 && ra == 0) { o0.x = 0.f; o0.y = 0.f; }
            if (ra < n_rows)
                *reinterpret_cast<float2*>(out + (size_t)ra * 128 + colc) = o0;
            if (ra + 8 < n_rows)
                *reinterpret_cast<float2*>(out + (size_t)(ra + 8) * 128 + colc) = o1;
        }
    }
}

// ---------------------------------------------------------------------------
extern "C" void kernel_launch(void* const* d_in, const int* in_sizes, int n_in,
                              void* d_out, int out_size) {
    const float* emb    = (const float*)d_in[0];
    const float* w1     = (const float*)d_in[1];
    const float* b1     = (const float*)d_in[2];
    const float* w2     = (const float*)d_in[3];
    const float* b2     = (const float*)d_in[4];
    const float* eps    = (const float*)d_in[5];
    const float* edge_w = (const float*)d_in[6];
    const int*   src    = (const int*)d_in[7];
    const int*   dst    = (const int*)d_in[8];

    int N = in_sizes[0] / DHID;
    int E = in_sizes[6];
    float* out = (float*)d_out;

    float *x1, *x2, *csr_w;
    int *cnt, *incl, *rowstart, *cursor, *bsums, *boffs, *csr_col;
    unsigned short *w1hi, *w1lo, *w2hi, *w2lo;
    cudaGetSymbolAddress((void**)&x1, g_x1);
    cudaGetSymbolAddress((void**)&x2, g_x2);
    cudaGetSymbolAddress((void**)&cnt, g_cnt);
    cudaGetSymbolAddress((void**)&incl, g_incl);
    cudaGetSymbolAddress((void**)&rowstart, g_rowstart);
    cudaGetSymbolAddress((void**)&cursor, g_cursor);
    cudaGetSymbolAddress((void**)&bsums, g_bsums);
    cudaGetSymbolAddress((void**)&boffs, g_boffs);
    cudaGetSymbolAddress((void**)&csr_col, g_col);
    cudaGetSymbolAddress((void**)&csr_w, g_w);
    cudaGetSymbolAddress((void**)&w1hi, g_w1hi);
    cudaGetSymbolAddress((void**)&w1lo, g_w1lo);
    cudaGetSymbolAddress((void**)&w2hi, g_w2hi);
    cudaGetSymbolAddress((void**)&w2lo, g_w2lo);

    static bool attr_set = false;
    if (!attr_set) {
        cudaFuncSetAttribute(mm_kernel,
                             cudaFuncAttributeMaxDynamicSharedMemorySize, SM_TOT);
        attr_set = true;
    }

    int nb = (N + SCAN_B - 1) / SCAN_B;
    int g_edges = (E + 255) / 256;
    int g_node  = (N + 255) / 256;
    int g_agg   = ((size_t)N * 32 + 255) / 256;
    int g_mm    = (N + 127) / 128;

    // ---- CSR build + weight prep ----
    zero_int_kernel<<<(N / 4 + 255) / 256, 256>>>(cnt, N / 4);
    count_kernel<<<g_edges, 256>>>(dst, cnt, E);
    prep_w_kernel<<<128, 256>>>(w1, w2);
    scan1_kernel<<<nb, SCAN_B>>>(cnt, incl, bsums, N);
    scan2_kernel<<<1, MAXBLK>>>(bsums, boffs, nb);
    scan3_kernel<<<g_node, 256>>>(incl, cnt, boffs, rowstart, cursor, N);
    fill_kernel<<<g_edges, 256>>>(src, dst, edge_w, cursor, csr_col, csr_w, E);

    // ---- layer 1: emb -> x1 (relu) ----
    agg_kernel<<<g_agg, 256>>>(emb, rowstart, cnt, csr_col, csr_w, eps, 0, x2, N);
    mm_kernel<<<g_mm, 256, SM_TOT>>>(x2, w1hi, w1lo, b1, x1, N, 1, 0);

    // ---- layer 2: x1 -> x2 (relu) ----
    agg_kernel<<<g_agg, 256>>>(x1, rowstart, cnt, csr_col, csr_w, eps, 1, x2, N);
    mm_kernel<<<g_mm, 256, SM_TOT>>>(x2, w2hi, w2lo, b2, x1, N, 1, 0);

    // ---- layer 3: x1 -> out (no relu, row 0 zeroed) ----
    agg_kernel<<<g_agg, 256>>>(x1, rowstart, cnt, csr_col, csr_w, eps, 2, x2, N);
    mm_kernel<<<g_mm, 256, SM_TOT>>>(x2, w2hi, w2lo, b2, out, N, 0, 1);
}